// round 1
// baseline (speedup 1.0000x reference)
#include <cuda_runtime.h>
#include <cstdint>
#include <cstdio>

#define HID    1024
#define NBATCH 4
#define SEQ    2048
#define NHEAD  16
#define DHEAD  64
#define MTOT   (NBATCH*SEQ)     // 8192
#define LSCALE 2.0f

// ---------------- scratch (device globals; no allocation allowed) ----------------
static __device__ uint32_t g_w  [3u*HID*HID];                          // folded weights, tf32 bits, [proj*1024+o][i]
static __device__ uint32_t g_x  [(size_t)MTOT*HID];                    // x in tf32 bits
static __device__ uint32_t g_qkv[(size_t)3*NBATCH*NHEAD*SEQ*DHEAD];    // tf32 [proj][b][h][t][d]

// ---------------- helpers ----------------
__device__ __forceinline__ uint32_t f2tf(float f){
    uint32_t u; asm("cvt.rna.tf32.f32 %0,%1;" : "=r"(u) : "f"(f)); return u;
}
__device__ __forceinline__ void cp16(uint32_t d, const void* s){
    asm volatile("cp.async.cg.shared.global [%0],[%1],16;" :: "r"(d), "l"(s));
}
__device__ __forceinline__ void cpcommit(){ asm volatile("cp.async.commit_group;"); }
__device__ __forceinline__ void cpwait0(){ asm volatile("cp.async.wait_group 0;"); }
__device__ __forceinline__ void cpwait1(){ asm volatile("cp.async.wait_group 1;"); }

__device__ __forceinline__ void mma8(float* c, uint32_t a0,uint32_t a1,uint32_t a2,uint32_t a3,
                                     uint32_t b0, uint32_t b1){
    asm volatile("mma.sync.aligned.m16n8k8.row.col.f32.tf32.tf32.f32 "
                 "{%0,%1,%2,%3},{%4,%5,%6,%7},{%8,%9},{%0,%1,%2,%3};"
                 : "+f"(c[0]),"+f"(c[1]),"+f"(c[2]),"+f"(c[3])
                 : "r"(a0),"r"(a1),"r"(a2),"r"(a3),"r"(b0),"r"(b1));
}

// ---------------- kernel 1: fold LoRA into weights (tf32) ----------------
__global__ void fold_k(int proj, const float* __restrict__ W,
                       const float* __restrict__ A, const float* __restrict__ Bm){
    int idx = blockIdx.x*256 + threadIdx.x;          // over 1024*1024
    int o = idx >> 10, i = idx & 1023;
    float acc = 0.f;
#pragma unroll
    for (int r = 0; r < 8; r++) acc += Bm[o*8 + r] * A[r*1024 + i];
    g_w[(size_t)proj*HID*HID + idx] = f2tf(W[idx] + LSCALE*acc);
}

// ---------------- kernel 2: convert x to tf32 ----------------
__global__ void cvtx_k(const float4* __restrict__ x){
    int idx = blockIdx.x*256 + threadIdx.x;          // over MTOT*HID/4
    float4 v = x[idx];
    uint4 u; u.x=f2tf(v.x); u.y=f2tf(v.y); u.z=f2tf(v.z); u.w=f2tf(v.w);
    reinterpret_cast<uint4*>(g_x)[idx] = u;
}

// ---------------- kernel 3: QKV GEMM  C[m][o] = x * W_eff^T + b ----------------
// M=8192, N=3072, K=1024. Block 128x128, K-chunk 32, double-buffered cp.async.
// 8 warps: 2x4 grid, warp tile 64x32. Output -> g_qkv[proj][b][h][t][d] (tf32).
#define SAST 36   // smem row stride (floats): (36*4)%16==0, conflict-free frags
__global__ __launch_bounds__(256,1) void gemm_k(const float* __restrict__ bq,
                                                const float* __restrict__ bk,
                                                const float* __restrict__ bv){
    extern __shared__ uint32_t sm[];
    uint32_t* As = sm;                       // [2][128][SAST]
    uint32_t* Bs = sm + 2*128*SAST;          // [2][128][SAST]
    const int tid  = threadIdx.x;
    const int lane = tid & 31;
    const int wid  = tid >> 5;
    const int grp  = lane >> 2, tig = lane & 3;
    const int m0 = blockIdx.x*128, n0 = blockIdx.y*128;
    const int wm = (wid>>2)*64, wn = (wid&3)*32;
    unsigned sbA = (unsigned)__cvta_generic_to_shared(As);
    unsigned sbB = (unsigned)__cvta_generic_to_shared(Bs);
    const uint32_t* gA = g_x + (size_t)m0*HID;
    const uint32_t* gB = g_w + (size_t)n0*HID;

    float c[4][4][4];
#pragma unroll
    for (int a=0;a<4;a++)
#pragma unroll
      for (int b2=0;b2<4;b2++)
#pragma unroll
        for (int i=0;i<4;i++) c[a][b2][i]=0.f;

    const int lrow = tid >> 3;          // 0..31
    const int lq4  = (tid & 7) * 4;     // 0..28

    auto loadst = [&](int kt, int st){
#pragma unroll
        for (int i=0;i<4;i++){
            int r = lrow + i*32;
            cp16(sbA + (unsigned)((st*128 + r)*SAST + lq4)*4, gA + (size_t)r*HID + kt*32 + lq4);
            cp16(sbB + (unsigned)((st*128 + r)*SAST + lq4)*4, gB + (size_t)r*HID + kt*32 + lq4);
        }
    };
    auto compute = [&](int st){
        const uint32_t* Ab = As + st*128*SAST;
        const uint32_t* Bb = Bs + st*128*SAST;
#pragma unroll
        for (int ks=0; ks<4; ks++){
            int k = ks*8;
            uint32_t af[4][4], bf[4][2];
#pragma unroll
            for (int mt=0; mt<4; mt++){
                const uint32_t* p = Ab + (wm + mt*16 + grp)*SAST + k + tig;
                af[mt][0]=p[0]; af[mt][1]=p[8*SAST]; af[mt][2]=p[4]; af[mt][3]=p[8*SAST+4];
            }
#pragma unroll
            for (int nt=0; nt<4; nt++){
                const uint32_t* p = Bb + (wn + nt*8 + grp)*SAST + k + tig;
                bf[nt][0]=p[0]; bf[nt][1]=p[4];
            }
#pragma unroll
            for (int mt=0; mt<4; mt++)
#pragma unroll
                for (int nt=0; nt<4; nt++)
                    mma8(c[mt][nt], af[mt][0],af[mt][1],af[mt][2],af[mt][3], bf[nt][0],bf[nt][1]);
        }
    };

    loadst(0,0); cpcommit();
    for (int kt=0; kt<32; kt++){
        if (kt < 31){ loadst(kt+1,(kt+1)&1); cpcommit(); cpwait1(); }
        else cpwait0();
        __syncthreads();
        compute(kt&1);
        __syncthreads();
    }

    // epilogue: +bias, scatter to g_qkv as tf32
    const int proj = n0 >> 10;
    const float* bias = (proj==0) ? bq : (proj==1 ? bk : bv);
#pragma unroll
    for (int mt=0; mt<4; mt++){
#pragma unroll
        for (int nt=0; nt<4; nt++){
            int n  = n0 + wn + nt*8 + 2*tig;
            int oo = n & 1023, hh = oo >> 6, dd = oo & 63;
            float bi0 = bias[oo], bi1 = bias[oo+1];
#pragma unroll
            for (int half=0; half<2; half++){
                int m = m0 + wm + mt*16 + grp + half*8;
                int bb = m >> 11, tt = m & 2047;
                size_t off = ((((size_t)proj*NBATCH + bb)*NHEAD + hh)*SEQ + tt)*DHEAD + dd;
                uint2 st2;
                st2.x = f2tf(c[mt][nt][half*2+0] + bi0);
                st2.y = f2tf(c[mt][nt][half*2+1] + bi1);
                *reinterpret_cast<uint2*>(g_qkv + off) = st2;
            }
        }
    }
}

// ---------------- kernel 4: causal flash attention ----------------
// Block: one (b,h), 128 q-rows. 8 warps, 16 q-rows each. Bc=64 kv per iter,
// double-buffered K/V. S/P/O via m16n8k8 tf32 mma; softmax fp32 in registers.
#define PAST 68   // smem row stride (floats)
__global__ __launch_bounds__(256,1) void attn_k(const float* __restrict__ mask,
                                                float* __restrict__ out){
    extern __shared__ uint32_t sm[];
    uint32_t* Qs = sm;                    // [128][PAST]
    uint32_t* Ks = Qs + 128*PAST;         // [2][64][PAST]
    uint32_t* Vs = Ks + 2*64*PAST;        // [2][64][PAST]
    uint32_t* Ps = Vs + 2*64*PAST;        // [128][PAST]
    unsigned sQ = (unsigned)__cvta_generic_to_shared(Qs);
    unsigned sK = (unsigned)__cvta_generic_to_shared(Ks);
    unsigned sV = (unsigned)__cvta_generic_to_shared(Vs);

    const int tid = threadIdx.x, lane = tid & 31, wid = tid >> 5;
    const int grp = lane >> 2, tig = lane & 3;
    const int qb = blockIdx.x, bh = blockIdx.y;
    const int b = bh >> 4, h = bh & 15;

    const uint32_t* Qg = g_qkv + ((size_t)(0*64 + bh)*SEQ + qb*128)*DHEAD;
    const uint32_t* Kg = g_qkv + ((size_t)(1*64 + bh)*SEQ)*DHEAD;
    const uint32_t* Vg = g_qkv + ((size_t)(2*64 + bh)*SEQ)*DHEAD;
    const float* mrow = mask + (size_t)b*SEQ;

    // load Q (128 rows x 64 cols)
    {
        int r = tid >> 4, q4 = (tid & 15)*4;
#pragma unroll
        for (int i=0;i<8;i++){
            int rr = r + i*16;
            cp16(sQ + (unsigned)(rr*PAST + q4)*4, Qg + (size_t)rr*64 + q4);
        }
    }
    auto loadkv = [&](int j, int st){
        int r = tid >> 4, q4 = (tid & 15)*4;
#pragma unroll
        for (int i=0;i<4;i++){
            int rr = r + i*16;
            cp16(sK + (unsigned)((st*64 + rr)*PAST + q4)*4, Kg + (size_t)(j*64 + rr)*64 + q4);
            cp16(sV + (unsigned)((st*64 + rr)*PAST + q4)*4, Vg + (size_t)(j*64 + rr)*64 + q4);
        }
    };

    const int qrow0 = qb*128 + wid*16;      // warp's first q row
    float mr0 = -1e30f, mr1 = -1e30f, l0 = 0.f, l1 = 0.f;
    float o[8][4];
#pragma unroll
    for (int nt=0;nt<8;nt++)
#pragma unroll
        for (int i=0;i<4;i++) o[nt][i]=0.f;

    loadkv(0,0); cpcommit();
    const int nj = 2*qb + 2;
    for (int j=0; j<nj; j++){
        if (j+1 < nj){ loadkv(j+1,(j+1)&1); cpcommit(); cpwait1(); }
        else cpwait0();
        __syncthreads();

        if (j*64 <= qrow0 + 15){   // causal warp-level skip
            const uint32_t* Kb = Ks + (j&1)*64*PAST;
            const uint32_t* Vb = Vs + (j&1)*64*PAST;
            float s[8][4];
#pragma unroll
            for (int nt=0;nt<8;nt++)
#pragma unroll
                for (int i=0;i<4;i++) s[nt][i]=0.f;

            // S = Q K^T
#pragma unroll
            for (int ks=0; ks<8; ks++){
                int k = ks*8;
                const uint32_t* qp = Qs + (wid*16 + grp)*PAST + k + tig;
                uint32_t a0=qp[0], a1=qp[8*PAST], a2=qp[4], a3=qp[8*PAST+4];
#pragma unroll
                for (int nt=0; nt<8; nt++){
                    const uint32_t* kp = Kb + (nt*8 + grp)*PAST + k + tig;
                    mma8(s[nt], a0,a1,a2,a3, kp[0], kp[4]);
                }
            }
            // scale + mask + online softmax
            int s0 = j*64;
            int q0 = qrow0 + grp, q1 = q0 + 8;
            float mx0 = -1e30f, mx1 = -1e30f;
#pragma unroll
            for (int nt=0; nt<8; nt++){
                int sc = s0 + nt*8 + 2*tig;
                float mk0 = __ldg(mrow + sc), mk1 = __ldg(mrow + sc + 1);
                float v0 = s[nt][0]*0.125f + mk0; if (sc   > q0) v0 = -1e30f;
                float v1 = s[nt][1]*0.125f + mk1; if (sc+1 > q0) v1 = -1e30f;
                float v2 = s[nt][2]*0.125f + mk0; if (sc   > q1) v2 = -1e30f;
                float v3 = s[nt][3]*0.125f + mk1; if (sc+1 > q1) v3 = -1e30f;
                s[nt][0]=v0; s[nt][1]=v1; s[nt][2]=v2; s[nt][3]=v3;
                mx0 = fmaxf(mx0, fmaxf(v0,v1));
                mx1 = fmaxf(mx1, fmaxf(v2,v3));
            }
            mx0 = fmaxf(mx0, __shfl_xor_sync(0xffffffffu, mx0, 1));
            mx0 = fmaxf(mx0, __shfl_xor_sync(0xffffffffu, mx0, 2));
            mx1 = fmaxf(mx1, __shfl_xor_sync(0xffffffffu, mx1, 1));
            mx1 = fmaxf(mx1, __shfl_xor_sync(0xffffffffu, mx1, 2));
            float mn0 = fmaxf(mr0, mx0), mn1 = fmaxf(mr1, mx1);
            float al0 = __expf(mr0 - mn0), al1 = __expf(mr1 - mn1);
            mr0 = mn0; mr1 = mn1;

            float ps0 = 0.f, ps1 = 0.f;
            uint32_t* pw = Ps + (wid*16 + grp)*PAST + 2*tig;
#pragma unroll
            for (int nt=0; nt<8; nt++){
                float p0 = __expf(s[nt][0]-mn0), p1 = __expf(s[nt][1]-mn0);
                float p2 = __expf(s[nt][2]-mn1), p3 = __expf(s[nt][3]-mn1);
                ps0 += p0 + p1; ps1 += p2 + p3;
                uint2 u0; u0.x = f2tf(p0); u0.y = f2tf(p1);
                uint2 u1; u1.x = f2tf(p2); u1.y = f2tf(p3);
                *reinterpret_cast<uint2*>(pw + nt*8)          = u0;
                *reinterpret_cast<uint2*>(pw + 8*PAST + nt*8) = u1;
            }
            ps0 += __shfl_xor_sync(0xffffffffu, ps0, 1);
            ps0 += __shfl_xor_sync(0xffffffffu, ps0, 2);
            ps1 += __shfl_xor_sync(0xffffffffu, ps1, 1);
            ps1 += __shfl_xor_sync(0xffffffffu, ps1, 2);
            l0 = l0*al0 + ps0; l1 = l1*al1 + ps1;
#pragma unroll
            for (int nt=0; nt<8; nt++){
                o[nt][0]*=al0; o[nt][1]*=al0; o[nt][2]*=al1; o[nt][3]*=al1;
            }
            __syncwarp();

            // O += P V
#pragma unroll
            for (int kc=0; kc<8; kc++){
                int k = kc*8;
                const uint32_t* pp = Ps + (wid*16 + grp)*PAST + k + tig;
                uint32_t a0=pp[0], a1=pp[8*PAST], a2=pp[4], a3=pp[8*PAST+4];
#pragma unroll
                for (int nt=0; nt<8; nt++){
                    const uint32_t* vp = Vb + (k + tig)*PAST + nt*8 + grp;
                    mma8(o[nt], a0,a1,a2,a3, vp[0], vp[4*PAST]);
                }
            }
        }
        __syncthreads();
    }

    // epilogue: normalize + store out[b][t][h*64+d]
    float i0 = 1.f/l0, i1 = 1.f/l1;
    int t0 = qrow0 + grp, t1 = t0 + 8;
    float* o0 = out + ((size_t)b*SEQ + t0)*HID + h*64;
    float* o1 = out + ((size_t)b*SEQ + t1)*HID + h*64;
#pragma unroll
    for (int nt=0; nt<8; nt++){
        int d = nt*8 + 2*tig;
        float2 f0; f0.x = o[nt][0]*i0; f0.y = o[nt][1]*i0;
        float2 f1; f1.x = o[nt][2]*i1; f1.y = o[nt][3]*i1;
        *reinterpret_cast<float2*>(o0 + d) = f0;
        *reinterpret_cast<float2*>(o1 + d) = f1;
    }
}

// ---------------- launch ----------------
extern "C" void kernel_launch(void* const* d_in, const int* in_sizes, int n_in,
                              void* d_out, int out_size){
    const float* x    = (const float*)d_in[0];
    const float* mask = (const float*)d_in[1];
    const float* Wq=(const float*)d_in[2],  *bq=(const float*)d_in[3];
    const float* Aq=(const float*)d_in[4],  *Bq=(const float*)d_in[5];
    const float* Wk=(const float*)d_in[6],  *bk=(const float*)d_in[7];
    const float* Ak=(const float*)d_in[8],  *Bk=(const float*)d_in[9];
    const float* Wv=(const float*)d_in[10], *bv=(const float*)d_in[11];
    const float* Av=(const float*)d_in[12], *Bv=(const float*)d_in[13];

    fold_k<<<4096,256>>>(0, Wq, Aq, Bq);
    fold_k<<<4096,256>>>(1, Wk, Ak, Bk);
    fold_k<<<4096,256>>>(2, Wv, Av, Bv);
    cvtx_k<<<8192,256>>>((const float4*)x);

    const int gemm_smem = 2*2*128*SAST*4;                     // 73728 B
    cudaFuncSetAttribute(gemm_k, cudaFuncAttributeMaxDynamicSharedMemorySize, gemm_smem);
    gemm_k<<<dim3(64,24),256,gemm_smem>>>(bq,bk,bv);

    const int attn_smem = (128*PAST + 4*64*PAST + 128*PAST)*4; // 139264 B
    cudaFuncSetAttribute(attn_k, cudaFuncAttributeMaxDynamicSharedMemorySize, attn_smem);
    attn_k<<<dim3(16,64),256,attn_smem>>>(mask, (float*)d_out);
}

// round 3
// speedup vs baseline: 1.2866x; 1.2866x over previous
#include <cuda_runtime.h>
#include <cstdint>

#define HID    1024
#define NBATCH 4
#define SEQ    2048
#define NHEAD  16
#define DHEAD  64
#define MTOT   (NBATCH*SEQ)     // 8192
#define LSCALE 2.0f

// ---------------- scratch (device globals; no allocation allowed) ----------------
static __device__ uint32_t g_w  [3u*HID*HID];                          // folded weights, tf32 bits
static __device__ uint32_t g_x  [(size_t)MTOT*HID];                    // x in tf32 bits
static __device__ uint32_t g_qkv[(size_t)3*NBATCH*NHEAD*SEQ*DHEAD];    // tf32 [proj][b][h][t][d]

// ---------------- helpers ----------------
__device__ __forceinline__ uint32_t f2tf(float f){
    uint32_t u; asm("cvt.rna.tf32.f32 %0,%1;" : "=r"(u) : "f"(f)); return u;
}
__device__ __forceinline__ void cp16(uint32_t d, const void* s){
    asm volatile("cp.async.cg.shared.global [%0],[%1],16;" :: "r"(d), "l"(s));
}
__device__ __forceinline__ void cpcommit(){ asm volatile("cp.async.commit_group;"); }
__device__ __forceinline__ void cpwait0(){ asm volatile("cp.async.wait_group 0;"); }
__device__ __forceinline__ void cpwait1(){ asm volatile("cp.async.wait_group 1;"); }

__device__ __forceinline__ void mma8(float* c, uint32_t a0,uint32_t a1,uint32_t a2,uint32_t a3,
                                     uint32_t b0, uint32_t b1){
    asm volatile("mma.sync.aligned.m16n8k8.row.col.f32.tf32.tf32.f32 "
                 "{%0,%1,%2,%3},{%4,%5,%6,%7},{%8,%9},{%0,%1,%2,%3};"
                 : "+f"(c[0]),"+f"(c[1]),"+f"(c[2]),"+f"(c[3])
                 : "r"(a0),"r"(a1),"r"(a2),"r"(a3),"r"(b0),"r"(b1));
}

// ---------------- kernel 1: fold LoRA into weights (tf32) ----------------
__global__ void fold_k(int proj, const float* __restrict__ W,
                       const float* __restrict__ A, const float* __restrict__ Bm){
    int idx = blockIdx.x*256 + threadIdx.x;          // over 1024*1024
    int o = idx >> 10, i = idx & 1023;
    float acc = 0.f;
#pragma unroll
    for (int r = 0; r < 8; r++) acc += Bm[o*8 + r] * A[r*1024 + i];
    g_w[(size_t)proj*HID*HID + idx] = f2tf(W[idx] + LSCALE*acc);
}

// ---------------- kernel 2: convert x to tf32 ----------------
__global__ void cvtx_k(const float4* __restrict__ x){
    int idx = blockIdx.x*256 + threadIdx.x;          // over MTOT*HID/4
    float4 v = x[idx];
    uint4 u; u.x=f2tf(v.x); u.y=f2tf(v.y); u.z=f2tf(v.z); u.w=f2tf(v.w);
    reinterpret_cast<uint4*>(g_x)[idx] = u;
}

// ---------------- kernel 3: QKV GEMM  C[m][o] = x * W_eff^T + b ----------------
// M=8192, N=3072, K=1024. Block 128x128, K-chunk 32, 3-stage cp.async pipeline,
// ONE __syncthreads per chunk. 8 warps: 2x4, warp tile 64x32.
#define SAST 36                    // smem row stride (words); 36 % 32 == 4 -> conflict-free frags
#define GST  (2*128*SAST)          // words per stage (A tile + B tile) = 36864 B
__global__ __launch_bounds__(256,2) void gemm_k(const float* __restrict__ bq,
                                                const float* __restrict__ bk,
                                                const float* __restrict__ bv){
    extern __shared__ uint32_t sm[];
    const int tid  = threadIdx.x;
    const int lane = tid & 31;
    const int wid  = tid >> 5;
    const int grp  = lane >> 2, tig = lane & 3;
    const int m0 = blockIdx.x*128, n0 = blockIdx.y*128;
    const int wm = (wid>>2)*64, wn = (wid&3)*32;
    unsigned sb = (unsigned)__cvta_generic_to_shared(sm);
    const uint32_t* gA = g_x + (size_t)m0*HID;
    const uint32_t* gB = g_w + (size_t)n0*HID;

    float c[4][4][4];
#pragma unroll
    for (int a=0;a<4;a++)
#pragma unroll
      for (int b2=0;b2<4;b2++)
#pragma unroll
        for (int i=0;i<4;i++) c[a][b2][i]=0.f;

    const int lrow = tid >> 3;          // 0..31
    const int lq4  = (tid & 7) * 4;     // 0..28

    auto load_tile = [&](int kt, int st){
        unsigned base = sb + (unsigned)(st*GST)*4;
#pragma unroll
        for (int i=0;i<4;i++){
            int r = lrow + i*32;
            cp16(base + (unsigned)(r*SAST + lq4)*4,                gA + (size_t)r*HID + kt*32 + lq4);
            cp16(base + (unsigned)((128 + r)*SAST + lq4)*4,        gB + (size_t)r*HID + kt*32 + lq4);
        }
    };
    auto compute = [&](int st){
        const uint32_t* Ab = sm + st*GST;
        const uint32_t* Bb = Ab + 128*SAST;
#pragma unroll
        for (int ks=0; ks<4; ks++){
            int k = ks*8;
            uint32_t af[4][4], bf[4][2];
#pragma unroll
            for (int mt=0; mt<4; mt++){
                const uint32_t* p = Ab + (wm + mt*16 + grp)*SAST + k + tig;
                af[mt][0]=p[0]; af[mt][1]=p[8*SAST]; af[mt][2]=p[4]; af[mt][3]=p[8*SAST+4];
            }
#pragma unroll
            for (int nt=0; nt<4; nt++){
                const uint32_t* p = Bb + (wn + nt*8 + grp)*SAST + k + tig;
                bf[nt][0]=p[0]; bf[nt][1]=p[4];
            }
#pragma unroll
            for (int mt=0; mt<4; mt++)
#pragma unroll
                for (int nt=0; nt<4; nt++)
                    mma8(c[mt][nt], af[mt][0],af[mt][1],af[mt][2],af[mt][3], bf[nt][0],bf[nt][1]);
        }
    };

    // 3-stage pipeline: groups complete in order, so wait_group(1) at iter kt
    // guarantees tile kt (group kt) is resident.
    load_tile(0,0); cpcommit();
    load_tile(1,1); cpcommit();
#pragma unroll 1
    for (int kt=0; kt<32; kt++){
        cpwait1();
        __syncthreads();                 // tile kt visible; stage (kt+2)%3 free
        if (kt+2 < 32) load_tile(kt+2, (kt+2)%3);
        cpcommit();                      // empty groups at the tail keep counts uniform
        compute(kt%3);
    }

    // epilogue: +bias, scatter to g_qkv as tf32
    const int proj = n0 >> 10;
    const float* bias = (proj==0) ? bq : (proj==1 ? bk : bv);
#pragma unroll
    for (int mt=0; mt<4; mt++){
#pragma unroll
        for (int nt=0; nt<4; nt++){
            int n  = n0 + wn + nt*8 + 2*tig;
            int oo = n & 1023, hh = oo >> 6, dd = oo & 63;
            float bi0 = bias[oo], bi1 = bias[oo+1];
#pragma unroll
            for (int half=0; half<2; half++){
                int m = m0 + wm + mt*16 + grp + half*8;
                int bb = m >> 11, tt = m & 2047;
                size_t off = ((((size_t)proj*NBATCH + bb)*NHEAD + hh)*SEQ + tt)*DHEAD + dd;
                uint2 st2;
                st2.x = f2tf(c[mt][nt][half*2+0] + bi0);
                st2.y = f2tf(c[mt][nt][half*2+1] + bi1);
                *reinterpret_cast<uint2*>(g_qkv + off) = st2;
            }
        }
    }
}

// ---------------- kernel 4: causal flash attention ----------------
// One (b,h) x 128 q-rows per CTA. 8 warps x 16 q-rows. Bc=64, double-buffered K/V.
// Q lives in register fragments (loaded once); the Q smem region is reused as P.
// smem = 128*PAST + 4*64*PAST floats = 104448 B  -> 2 CTAs/SM.
#define PAST 68   // smem row stride (words); 68 % 32 == 4 -> conflict-free frags
__global__ __launch_bounds__(256,2) void attn_k(const float* __restrict__ mask,
                                                float* __restrict__ out){
    extern __shared__ uint32_t sm[];
    uint32_t* QP = sm;                    // [128][PAST] : Q first, then reused as P
    uint32_t* Ks = QP + 128*PAST;         // [2][64][PAST]
    uint32_t* Vs = Ks + 2*64*PAST;        // [2][64][PAST]
    unsigned sQ = (unsigned)__cvta_generic_to_shared(QP);
    unsigned sK = (unsigned)__cvta_generic_to_shared(Ks);
    unsigned sV = (unsigned)__cvta_generic_to_shared(Vs);

    const int tid = threadIdx.x, lane = tid & 31, wid = tid >> 5;
    const int grp = lane >> 2, tig = lane & 3;
    const int bh = blockIdx.x;
    const int qb = 15 - blockIdx.y;       // heaviest blocks launch first
    const int b = bh >> 4, h = bh & 15;

    const uint32_t* Qg = g_qkv + ((size_t)(0*64 + bh)*SEQ + qb*128)*DHEAD;
    const uint32_t* Kg = g_qkv + ((size_t)(1*64 + bh)*SEQ)*DHEAD;
    const uint32_t* Vg = g_qkv + ((size_t)(2*64 + bh)*SEQ)*DHEAD;
    const float* mrow = mask + (size_t)b*SEQ;

    // Q -> smem (group 0)
    {
        int r = tid >> 4, q4 = (tid & 15)*4;
#pragma unroll
        for (int i=0;i<8;i++){
            int rr = r + i*16;
            cp16(sQ + (unsigned)(rr*PAST + q4)*4, Qg + (size_t)rr*64 + q4);
        }
    }
    cpcommit();
    auto loadkv = [&](int j, int st){
        int r = tid >> 4, q4 = (tid & 15)*4;
#pragma unroll
        for (int i=0;i<4;i++){
            int rr = r + i*16;
            cp16(sK + (unsigned)((st*64 + rr)*PAST + q4)*4, Kg + (size_t)(j*64 + rr)*64 + q4);
            cp16(sV + (unsigned)((st*64 + rr)*PAST + q4)*4, Vg + (size_t)(j*64 + rr)*64 + q4);
        }
    };
    loadkv(0,0); cpcommit();              // group 1

    // wait for Q (group 0), publish, pull Q fragments into registers
    cpwait1();
    __syncthreads();
    uint32_t qf[8][4];
#pragma unroll
    for (int kg=0; kg<8; kg++){
        const uint32_t* qp = QP + (wid*16 + grp)*PAST + kg*8 + tig;
        qf[kg][0]=qp[0]; qf[kg][1]=qp[8*PAST]; qf[kg][2]=qp[4]; qf[kg][3]=qp[8*PAST+4];
    }
    // From here QP is the P buffer. Each warp reads/writes ONLY its own 16 rows,
    // so no extra barrier is needed between qf reads and P writes.

    const int qrow0 = qb*128 + wid*16;
    float mr0 = -1e30f, mr1 = -1e30f, l0 = 0.f, l1 = 0.f;
    float o[8][4];
#pragma unroll
    for (int nt=0;nt<8;nt++)
#pragma unroll
        for (int i=0;i<4;i++) o[nt][i]=0.f;

    const int nj = 2*qb + 2;
#pragma unroll 1
    for (int j=0; j<nj; j++){
        if (j+1 < nj){ loadkv(j+1,(j+1)&1); cpcommit(); cpwait1(); }
        else cpwait0();
        __syncthreads();

        if (j*64 <= qrow0 + 15){          // causal warp-level skip
            const uint32_t* Kb = Ks + (j&1)*64*PAST;
            const uint32_t* Vb = Vs + (j&1)*64*PAST;
            float s[8][4];
#pragma unroll
            for (int nt=0;nt<8;nt++)
#pragma unroll
                for (int i=0;i<4;i++) s[nt][i]=0.f;

            // S = Q K^T
#pragma unroll
            for (int ks=0; ks<8; ks++){
                int k = ks*8;
#pragma unroll
                for (int nt=0; nt<8; nt++){
                    const uint32_t* kp = Kb + (nt*8 + grp)*PAST + k + tig;
                    mma8(s[nt], qf[ks][0],qf[ks][1],qf[ks][2],qf[ks][3], kp[0], kp[4]);
                }
            }
            // scale + mask + online softmax
            int s0 = j*64;
            int q0 = qrow0 + grp, q1 = q0 + 8;
            float mx0 = -1e30f, mx1 = -1e30f;
#pragma unroll
            for (int nt=0; nt<8; nt++){
                int sc = s0 + nt*8 + 2*tig;
                float mk0 = __ldg(mrow + sc), mk1 = __ldg(mrow + sc + 1);
                float v0 = s[nt][0]*0.125f + mk0; if (sc   > q0) v0 = -1e30f;
                float v1 = s[nt][1]*0.125f + mk1; if (sc+1 > q0) v1 = -1e30f;
                float v2 = s[nt][2]*0.125f + mk0; if (sc   > q1) v2 = -1e30f;
                float v3 = s[nt][3]*0.125f + mk1; if (sc+1 > q1) v3 = -1e30f;
                s[nt][0]=v0; s[nt][1]=v1; s[nt][2]=v2; s[nt][3]=v3;
                mx0 = fmaxf(mx0, fmaxf(v0,v1));
                mx1 = fmaxf(mx1, fmaxf(v2,v3));
            }
            mx0 = fmaxf(mx0, __shfl_xor_sync(0xffffffffu, mx0, 1));
            mx0 = fmaxf(mx0, __shfl_xor_sync(0xffffffffu, mx0, 2));
            mx1 = fmaxf(mx1, __shfl_xor_sync(0xffffffffu, mx1, 1));
            mx1 = fmaxf(mx1, __shfl_xor_sync(0xffffffffu, mx1, 2));
            float mn0 = fmaxf(mr0, mx0), mn1 = fmaxf(mr1, mx1);
            float al0 = __expf(mr0 - mn0), al1 = __expf(mr1 - mn1);
            mr0 = mn0; mr1 = mn1;

            float ps0 = 0.f, ps1 = 0.f;
            uint32_t* pw = QP + (wid*16 + grp)*PAST + 2*tig;
#pragma unroll
            for (int nt=0; nt<8; nt++){
                float p0 = __expf(s[nt][0]-mn0), p1 = __expf(s[nt][1]-mn0);
                float p2 = __expf(s[nt][2]-mn1), p3 = __expf(s[nt][3]-mn1);
                ps0 += p0 + p1; ps1 += p2 + p3;
                uint2 u0; u0.x = f2tf(p0); u0.y = f2tf(p1);
                uint2 u1; u1.x = f2tf(p2); u1.y = f2tf(p3);
                *reinterpret_cast<uint2*>(pw + nt*8)          = u0;
                *reinterpret_cast<uint2*>(pw + 8*PAST + nt*8) = u1;
            }
            ps0 += __shfl_xor_sync(0xffffffffu, ps0, 1);
            ps0 += __shfl_xor_sync(0xffffffffu, ps0, 2);
            ps1 += __shfl_xor_sync(0xffffffffu, ps1, 1);
            ps1 += __shfl_xor_sync(0xffffffffu, ps1, 2);
            l0 = l0*al0 + ps0; l1 = l1*al1 + ps1;
#pragma unroll
            for (int nt=0; nt<8; nt++){
                o[nt][0]*=al0; o[nt][1]*=al0; o[nt][2]*=al1; o[nt][3]*=al1;
            }
            __syncwarp();

            // O += P V
#pragma unroll
            for (int kc=0; kc<8; kc++){
                int k = kc*8;
                const uint32_t* pp = QP + (wid*16 + grp)*PAST + k + tig;
                uint32_t a0=pp[0], a1=pp[8*PAST], a2=pp[4], a3=pp[8*PAST+4];
#pragma unroll
                for (int nt=0; nt<8; nt++){
                    const uint32_t* vp = Vb + (k + tig)*PAST + nt*8 + grp;
                    mma8(o[nt], a0,a1,a2,a3, vp[0], vp[4*PAST]);
                }
            }
        }
        __syncthreads();
    }

    // epilogue: normalize + store out[b][t][h*64+d]
    float i0 = 1.f/l0, i1 = 1.f/l1;
    int t0 = qrow0 + grp, t1 = t0 + 8;
    float* o0 = out + ((size_t)b*SEQ + t0)*HID + h*64;
    float* o1 = out + ((size_t)b*SEQ + t1)*HID + h*64;
#pragma unroll
    for (int nt=0; nt<8; nt++){
        int d = nt*8 + 2*tig;
        float2 f0; f0.x = o[nt][0]*i0; f0.y = o[nt][1]*i0;
        float2 f1; f1.x = o[nt][2]*i1; f1.y = o[nt][3]*i1;
        *reinterpret_cast<float2*>(o0 + d) = f0;
        *reinterpret_cast<float2*>(o1 + d) = f1;
    }
}

// ---------------- launch ----------------
extern "C" void kernel_launch(void* const* d_in, const int* in_sizes, int n_in,
                              void* d_out, int out_size){
    const float* x    = (const float*)d_in[0];
    const float* mask = (const float*)d_in[1];
    const float* Wq=(const float*)d_in[2],  *bq=(const float*)d_in[3];
    const float* Aq=(const float*)d_in[4],  *Bq=(const float*)d_in[5];
    const float* Wk=(const float*)d_in[6],  *bk=(const float*)d_in[7];
    const float* Ak=(const float*)d_in[8],  *Bk=(const float*)d_in[9];
    const float* Wv=(const float*)d_in[10], *bv=(const float*)d_in[11];
    const float* Av=(const float*)d_in[12], *Bv=(const float*)d_in[13];

    fold_k<<<4096,256>>>(0, Wq, Aq, Bq);
    fold_k<<<4096,256>>>(1, Wk, Ak, Bk);
    fold_k<<<4096,256>>>(2, Wv, Av, Bv);
    cvtx_k<<<8192,256>>>((const float4*)x);

    const int gemm_smem = 3*GST*4;                            // 110592 B
    cudaFuncSetAttribute(gemm_k, cudaFuncAttributeMaxDynamicSharedMemorySize, gemm_smem);
    gemm_k<<<dim3(64,24),256,gemm_smem>>>(bq,bk,bv);

    const int attn_smem = (128*PAST + 4*64*PAST)*4;           // 104448 B
    cudaFuncSetAttribute(attn_k, cudaFuncAttributeMaxDynamicSharedMemorySize, attn_smem);
    attn_k<<<dim3(64,16),256,attn_smem>>>(mask, (float*)d_out);
}